// round 8
// baseline (speedup 1.0000x reference)
#include <cuda_runtime.h>

#define S 2048
#define C 4096
#define K 4
#define SCHUNK 8            // samples per block
#define BLKCH 1024          // channels per block (256 thr * 4 ch)

// Per-sample params, block-shared (tiny: 384 B).
struct Params {
    float4 w0[SCHUNK];      // tap0 weight per k
    float4 w1[SCHUNK];      // tap1 weight per k
    int4   r [SCHUNK];      // tap offset r = mi+4 in [0,7], per k
};

// Compile-time tap wiring: taps w[R..R+4] -> 8 FFMA, pure register picks.
template<int R>
__device__ __forceinline__ void taps(const float (&w)[12], float W0, float W1,
                                     float& a0, float& a1, float& a2, float& a3) {
    a0 = fmaf(W0, w[R + 0], fmaf(W1, w[R + 1], a0));
    a1 = fmaf(W0, w[R + 1], fmaf(W1, w[R + 2], a1));
    a2 = fmaf(W0, w[R + 2], fmaf(W1, w[R + 3], a2));
    a3 = fmaf(W0, w[R + 3], fmaf(W1, w[R + 4], a3));
}

// Warp-uniform 8-way switch (R is sample-uniform): no divergence, no tap loads.
__device__ __forceinline__ void tap_switch(int R, const float (&w)[12], float W0, float W1,
                                           float& a0, float& a1, float& a2, float& a3) {
    switch (R) {
        case 0:  taps<0>(w, W0, W1, a0, a1, a2, a3); break;
        case 1:  taps<1>(w, W0, W1, a0, a1, a2, a3); break;
        case 2:  taps<2>(w, W0, W1, a0, a1, a2, a3); break;
        case 3:  taps<3>(w, W0, W1, a0, a1, a2, a3); break;
        case 4:  taps<4>(w, W0, W1, a0, a1, a2, a3); break;
        case 5:  taps<5>(w, W0, W1, a0, a1, a2, a3); break;
        case 6:  taps<6>(w, W0, W1, a0, a1, a2, a3); break;
        default: taps<7>(w, W0, W1, a0, a1, a2, a3); break;
    }
}

// Thread owns 4 consecutive channels; its 12-word window per component
// (comp[k][c-4 .. c+7], zero-padded at row edges) lives in REGISTERS.
// Tap index for channel c+j, component k: window[j + r_k], r_k in [0,7].
__global__ void __launch_bounds__(256, 3)
smf_kernel(const float* __restrict__ comp,      // (K, C)
           const float* __restrict__ contrib,   // (S, K)
           const float* __restrict__ shift,     // (S, K)
           float* __restrict__ out)             // (S, C)
{
    __shared__ Params p;

    const int tid = threadIdx.x;
    const int B0  = blockIdx.x * BLKCH;
    const int s0  = blockIdx.y * SCHUNK;

    // ---- params: thread t<32 handles (sample t>>2, comp t&3) ----
    if (tid < SCHUNK * K) {
        const int sl = tid >> 2;
        const int kk = tid & 3;
        const float sh = __ldg(&shift[(s0 + sl) * K + kk]);
        const float wc = __ldg(&contrib[(s0 + sl) * K + kk]);
        const float m  = floorf(sh);
        const float f  = sh - m;
        int r = (int)m + 4;                      // shift in [-4,4) -> r in [0,7]
        r = max(0, min(7, r));
        const float w1 = wc * f;
        reinterpret_cast<float*>(&p.w0[sl])[kk] = wc - w1;
        reinterpret_cast<float*>(&p.w1[sl])[kk] = w1;
        reinterpret_cast<int*>(&p.r[sl])[kk]    = r;
    }

    // ---- register window: 3 aligned LDG.128 per component ----
    const int c  = B0 + 4 * tid;                 // thread's first channel
    const int i4 = c >> 2;
    float w[K][12];
#pragma unroll
    for (int k = 0; k < K; k++) {
        const float4* c4 = reinterpret_cast<const float4*>(comp + k * C);
        const float4 z  = make_float4(0.f, 0.f, 0.f, 0.f);
        const float4 va = (i4 > 0)         ? __ldg(&c4[i4 - 1]) : z;
        const float4 vb = __ldg(&c4[i4]);
        const float4 vc = (i4 < C / 4 - 1) ? __ldg(&c4[i4 + 1]) : z;
        w[k][0] = va.x; w[k][1]  = va.y; w[k][2]  = va.z; w[k][3]  = va.w;
        w[k][4] = vb.x; w[k][5]  = vb.y; w[k][6]  = vb.z; w[k][7]  = vb.w;
        w[k][8] = vc.x; w[k][9]  = vc.y; w[k][10] = vc.z; w[k][11] = vc.w;
    }
    __syncthreads();

    float* op = out + (size_t)s0 * C + c;

#pragma unroll 1
    for (int sl = 0; sl < SCHUNK; sl++) {
        const float4 W0 = p.w0[sl];              // broadcast LDS.128
        const float4 W1 = p.w1[sl];
        const int4   R  = p.r[sl];

        float a0 = 0.f, a1 = 0.f, a2 = 0.f, a3 = 0.f;
        tap_switch(R.x, w[0], W0.x, W1.x, a0, a1, a2, a3);
        tap_switch(R.y, w[1], W0.y, W1.y, a0, a1, a2, a3);
        tap_switch(R.z, w[2], W0.z, W1.z, a0, a1, a2, a3);
        tap_switch(R.w, w[3], W0.w, W1.w, a0, a1, a2, a3);

        *reinterpret_cast<float4*>(op) = make_float4(a0, a1, a2, a3);
        op += C;
    }
}

extern "C" void kernel_launch(void* const* d_in, const int* in_sizes, int n_in,
                              void* d_out, int out_size) {
    // metadata order: inputs (unused), components, contributions, shift
    const float* comp    = (const float*)d_in[1];
    const float* contrib = (const float*)d_in[2];
    const float* shift   = (const float*)d_in[3];
    float*       out     = (float*)d_out;

    dim3 grid(C / BLKCH, S / SCHUNK);   // (4, 256) = 1024 blocks
    smf_kernel<<<grid, 256>>>(comp, contrib, shift, out);
}

// round 10
// speedup vs baseline: 1.0523x; 1.0523x over previous
#include <cuda_runtime.h>

#define S 2048
#define C 4096
#define K 4
#define SCHUNK 8            // samples per block
#define BLKCH 512           // channels per block (4 warps * 128)
#define NW 4                // warps per block
#define SUBW 36             // de-interleave sub-array stride (words) per k
#define KW (4 * SUBW)       // words per k per warp tile (144)
#define WTILE (K * KW)      // words per warp tile (576)

// Warp-private per-sample params.
struct WParams {
    float4 w0[SCHUNK];         // tap0 weight per k
    float4 w1[SCHUNK];         // tap1 weight per k
    int4   off[SCHUNK][K];     // byte offsets f(r+j)*4, j=0..3 (j=4 is off.x+4)
};

// Warp-autonomous: each warp stages its own 128-channel (+halo) tile and its
// own params into warp-private smem; only __syncwarp needed. Tap word
// 4*lane + x (x in [0,11]) lives at (x&3)*SUBW + (x>>2) + lane: lane-consecutive
// LDS (conflict-free), sample-uniform precomputed byte offset, f(x+4)=f(x)+1.
__global__ void __launch_bounds__(128, 12)
smf_kernel(const float* __restrict__ comp,      // (K, C)
           const float* __restrict__ contrib,   // (S, K)
           const float* __restrict__ shift,     // (S, K)
           float* __restrict__ out)             // (S, C)
{
    __shared__ float   s_tile[NW][WTILE];
    __shared__ WParams s_prm[NW];

    const int tid  = threadIdx.x;
    const int warp = tid >> 5;
    const int lane = tid & 31;
    const int wc0  = blockIdx.x * BLKCH + warp * 128;   // warp's first channel
    const int s0   = blockIdx.y * SCHUNK;

    // ---- param compute: lane l handles (sample l>>2, comp l&3) ----
    {
        const int sl = lane >> 2;
        const int kk = lane & 3;
        const float sh = __ldg(&shift[(s0 + sl) * K + kk]);
        const float w  = __ldg(&contrib[(s0 + sl) * K + kk]);
        const float m  = floorf(sh);
        const float f  = sh - m;
        int r = (int)m + 4;                    // shift in [-4,4) -> r in [0,7]
        r = max(0, min(7, r));
        const float w1 = w * f;
        reinterpret_cast<float*>(&s_prm[warp].w0[sl])[kk] = w - w1;
        reinterpret_cast<float*>(&s_prm[warp].w1[sl])[kk] = w1;
        int o[4];
#pragma unroll
        for (int j = 0; j < 4; j++) {
            const int x = r + j;
            o[j] = ((x & 3) * SUBW + (x >> 2)) * 4;    // byte offset
        }
        s_prm[warp].off[sl][kk] = make_int4(o[0], o[1], o[2], o[3]);
    }

    // ---- stage warp tile: 140 words per k = 35 float4s.
    // float4 q (q=0..34) covers words t=4q+u -> phys u*SUBW + q.
    // Lanes 0..31 take q=lane; lanes 0..2 additionally take q=32+lane.
    float* wt = s_tile[warp];
    {
        const int i4base = (wc0 - 4) >> 2;     // arithmetic shift floors -4 -> -1
        const int C4 = C / 4;
#pragma unroll
        for (int k = 0; k < K; k++) {
            const float4* c4 = reinterpret_cast<const float4*>(comp + k * C);
            // q = lane
            {
                const int i4 = i4base + lane;
                float4 v = make_float4(0.f, 0.f, 0.f, 0.f);
                if (i4 >= 0 && i4 < C4) v = __ldg(&c4[i4]);
                float* b = &wt[k * KW + lane];
                b[0 * SUBW] = v.x;
                b[1 * SUBW] = v.y;
                b[2 * SUBW] = v.z;
                b[3 * SUBW] = v.w;
            }
            // q = 32 + lane (lanes 0..2): upper halo tail
            if (lane < 3) {
                const int q  = 32 + lane;
                const int i4 = i4base + q;
                float4 v = make_float4(0.f, 0.f, 0.f, 0.f);
                if (i4 >= 0 && i4 < C4) v = __ldg(&c4[i4]);
                float* b = &wt[k * KW + q];
                b[0 * SUBW] = v.x;
                b[1 * SUBW] = v.y;
                b[2 * SUBW] = v.z;
                b[3 * SUBW] = v.w;
            }
        }
    }
    __syncwarp();

    // per-k tap base pointers (byte-addressed)
    const char* tb0 = reinterpret_cast<const char*>(&wt[0 * KW + lane]);
    const char* tb1 = reinterpret_cast<const char*>(&wt[1 * KW + lane]);
    const char* tb2 = reinterpret_cast<const char*>(&wt[2 * KW + lane]);
    const char* tb3 = reinterpret_cast<const char*>(&wt[3 * KW + lane]);

    float* op = out + (size_t)s0 * C + wc0 + 4 * lane;

#pragma unroll 2
    for (int sl = 0; sl < SCHUNK; sl++) {
        const float4 W0 = s_prm[warp].w0[sl];      // broadcast LDS.128
        const float4 W1 = s_prm[warp].w1[sl];

        float a0 = 0.f, a1 = 0.f, a2 = 0.f, a3 = 0.f;

#pragma unroll
        for (int k = 0; k < K; k++) {
            const int4 off = s_prm[warp].off[sl][k];   // broadcast LDS.128
            const char* tb = (k == 0) ? tb0 : (k == 1) ? tb1 : (k == 2) ? tb2 : tb3;
            const float w0 = (k == 0) ? W0.x : (k == 1) ? W0.y : (k == 2) ? W0.z : W0.w;
            const float w1 = (k == 0) ? W1.x : (k == 1) ? W1.y : (k == 2) ? W1.z : W1.w;

            const float h0 = *reinterpret_cast<const float*>(tb + off.x);
            const float h1 = *reinterpret_cast<const float*>(tb + off.y);
            const float h2 = *reinterpret_cast<const float*>(tb + off.z);
            const float h3 = *reinterpret_cast<const float*>(tb + off.w);
            const float h4 = *reinterpret_cast<const float*>(tb + off.x + 4); // f(r+4)=f(r)+1

            a0 = fmaf(w0, h0, fmaf(w1, h1, a0));
            a1 = fmaf(w0, h1, fmaf(w1, h2, a1));
            a2 = fmaf(w0, h2, fmaf(w1, h3, a2));
            a3 = fmaf(w0, h3, fmaf(w1, h4, a3));
        }

        *reinterpret_cast<float4*>(op) = make_float4(a0, a1, a2, a3);
        op += C;
    }
}

extern "C" void kernel_launch(void* const* d_in, const int* in_sizes, int n_in,
                              void* d_out, int out_size) {
    // metadata order: inputs (unused), components, contributions, shift
    const float* comp    = (const float*)d_in[1];
    const float* contrib = (const float*)d_in[2];
    const float* shift   = (const float*)d_in[3];
    float*       out     = (float*)d_out;

    static bool configured = false;
    if (!configured) {
        cudaFuncSetAttribute(smf_kernel,
                             cudaFuncAttributePreferredSharedMemoryCarveout, 100);
        configured = true;
    }

    dim3 grid(C / BLKCH, S / SCHUNK);   // (8, 256) = 2048 blocks
    smf_kernel<<<grid, 128>>>(comp, contrib, shift, out);
}